// round 2
// baseline (speedup 1.0000x reference)
#include <cuda_runtime.h>
#include <cuda_bf16.h>
#include <math.h>

// ---------------- problem constants ----------------
constexpr int CB    = 2;
constexpr int CQ    = 1024;
constexpr int CHID  = 2048;
constexpr int CNH   = 32;
constexpr int CNKV  = 8;
constexpr int CHD   = 64;
constexpr int CG    = 4;      // GROUPS = NH/NKV
constexpr int CKB   = 512;
constexpr int CTOPK = 100;
#define SCALE_F  0.125f                 // 1/sqrt(64)
#define KB_BIAS  1.6331544f             // log(512) - log(100)

// ---------------- scratch (device globals; no cudaMalloc allowed) ----------------
__device__ float g_q   [CB*CQ*CNH*CHD];    // roped Q        [B,Q,NH,HD]
__device__ float g_kbq [CB*CQ*CNH*CHD];    // KB query (no rope)
__device__ float g_k   [CB*CQ*CNKV*CHD];   // roped K        [B,Q,NKV,HD]
__device__ float g_v   [CB*CQ*CNKV*CHD];
__device__ float g_kbk [CB*CKB*CNKV*CHD];  // [B,KB,NKV,HD]
__device__ float g_kbv [CB*CKB*CNKV*CHD];
__device__ float g_attn[CB*CQ*CNH*CHD];    // attention output, [B,Q,NH*HD]
__device__ float g_qsum_part[CB*16*CNKV*CHD];
__device__ float g_qsum[CB*CNKV*CHD];
__device__ float g_scores[CB*CKB];
__device__ int   g_topidx[CB*CTOPK];

// ---------------- bf16 split helpers ----------------
__device__ __forceinline__ unsigned pack_bf16(__nv_bfloat16 a, __nv_bfloat16 b) {
    unsigned r;
    unsigned short lo = *reinterpret_cast<unsigned short*>(&a);
    unsigned short hi = *reinterpret_cast<unsigned short*>(&b);
    r = (unsigned)lo | ((unsigned)hi << 16);
    return r;
}

__device__ __forceinline__ void mma16816(float* c, const unsigned* a, const unsigned* b) {
    asm volatile(
        "mma.sync.aligned.m16n8k16.row.col.f32.bf16.bf16.f32 "
        "{%0,%1,%2,%3}, {%4,%5,%6,%7}, {%8,%9}, {%0,%1,%2,%3};"
        : "+f"(c[0]), "+f"(c[1]), "+f"(c[2]), "+f"(c[3])
        : "r"(a[0]), "r"(a[1]), "r"(a[2]), "r"(a[3]), "r"(b[0]), "r"(b[1]));
}

// ---------------- bf16-split 3-pass tensor GEMM ----------------
// C[M,N] = A[M,K] @ B[K,N], fp32 in/out, computed as Ah*Bh + Ah*Bl + Al*Bh.
// CTA tile 128x128, BK=32, 8 warps (4x2), warp tile 32x64.
constexpr int GBK  = 32;
constexpr int SSTR = 40;   // smem row stride (bf16 elems) -> conflict-free frag loads

__global__ __launch_bounds__(256)
void gemm_bf16x3_kernel(const float* __restrict__ A, const float* __restrict__ Bm,
                        float* __restrict__ C, int M, int N, int K) {
    __shared__ __align__(16) __nv_bfloat16 As[2][128][SSTR];  // [hi/lo][m][k]
    __shared__ __align__(16) __nv_bfloat16 Bs[2][128][SSTR];  // [hi/lo][n][k]

    const int tid  = threadIdx.x;
    const int wid  = tid >> 5, lane = tid & 31;
    const int wm   = wid >> 1, wn = wid & 1;      // 4x2 warp grid
    const int gid  = lane >> 2, tig = lane & 3;
    const int rb   = blockIdx.y * 128;
    const int cb   = blockIdx.x * 128;

    float acc[2][8][4];
    #pragma unroll
    for (int mt = 0; mt < 2; mt++)
        #pragma unroll
        for (int nt = 0; nt < 8; nt++)
            #pragma unroll
            for (int i = 0; i < 4; i++) acc[mt][nt][i] = 0.f;

    for (int k0 = 0; k0 < K; k0 += GBK) {
        // ---- load + split A tile: 128 rows x 32 cols ----
        #pragma unroll
        for (int it = 0; it < 4; it++) {
            int i   = tid + it * 256;          // 0..1023 float4s
            int row = i >> 3, c0 = (i & 7) * 4;
            float4 v = *(const float4*)&A[(size_t)(rb + row) * K + k0 + c0];
            __nv_bfloat16 h0 = __float2bfloat16_rn(v.x);
            __nv_bfloat16 h1 = __float2bfloat16_rn(v.y);
            __nv_bfloat16 h2 = __float2bfloat16_rn(v.z);
            __nv_bfloat16 h3 = __float2bfloat16_rn(v.w);
            __nv_bfloat16 l0 = __float2bfloat16_rn(v.x - __bfloat162float(h0));
            __nv_bfloat16 l1 = __float2bfloat16_rn(v.y - __bfloat162float(h1));
            __nv_bfloat16 l2 = __float2bfloat16_rn(v.z - __bfloat162float(h2));
            __nv_bfloat16 l3 = __float2bfloat16_rn(v.w - __bfloat162float(h3));
            *(unsigned*)&As[0][row][c0]     = pack_bf16(h0, h1);
            *(unsigned*)&As[0][row][c0 + 2] = pack_bf16(h2, h3);
            *(unsigned*)&As[1][row][c0]     = pack_bf16(l0, l1);
            *(unsigned*)&As[1][row][c0 + 2] = pack_bf16(l2, l3);
        }
        // ---- load + split B tile (transpose to [n][k]): 32 rows x 128 cols ----
        #pragma unroll
        for (int it = 0; it < 4; it++) {
            int i  = tid + it * 256;           // 0..1023 float4s
            int kr = i >> 5, n0 = (i & 31) * 4;
            float4 v = *(const float4*)&Bm[(size_t)(k0 + kr) * N + cb + n0];
            float vv[4] = {v.x, v.y, v.z, v.w};
            #pragma unroll
            for (int j = 0; j < 4; j++) {
                __nv_bfloat16 h = __float2bfloat16_rn(vv[j]);
                __nv_bfloat16 l = __float2bfloat16_rn(vv[j] - __bfloat162float(h));
                Bs[0][n0 + j][kr] = h;
                Bs[1][n0 + j][kr] = l;
            }
        }
        __syncthreads();

        // ---- compute: two k16 steps ----
        #pragma unroll
        for (int kk = 0; kk < GBK; kk += 16) {
            unsigned ah[2][4], al[2][4], bh[8][2], bl[8][2];
            #pragma unroll
            for (int mt = 0; mt < 2; mt++) {
                int r0 = wm * 32 + mt * 16;
                ah[mt][0] = *(const unsigned*)&As[0][r0 + gid    ][kk + tig * 2];
                ah[mt][1] = *(const unsigned*)&As[0][r0 + gid + 8][kk + tig * 2];
                ah[mt][2] = *(const unsigned*)&As[0][r0 + gid    ][kk + tig * 2 + 8];
                ah[mt][3] = *(const unsigned*)&As[0][r0 + gid + 8][kk + tig * 2 + 8];
                al[mt][0] = *(const unsigned*)&As[1][r0 + gid    ][kk + tig * 2];
                al[mt][1] = *(const unsigned*)&As[1][r0 + gid + 8][kk + tig * 2];
                al[mt][2] = *(const unsigned*)&As[1][r0 + gid    ][kk + tig * 2 + 8];
                al[mt][3] = *(const unsigned*)&As[1][r0 + gid + 8][kk + tig * 2 + 8];
            }
            #pragma unroll
            for (int nt = 0; nt < 8; nt++) {
                int n0 = wn * 64 + nt * 8;
                bh[nt][0] = *(const unsigned*)&Bs[0][n0 + gid][kk + tig * 2];
                bh[nt][1] = *(const unsigned*)&Bs[0][n0 + gid][kk + tig * 2 + 8];
                bl[nt][0] = *(const unsigned*)&Bs[1][n0 + gid][kk + tig * 2];
                bl[nt][1] = *(const unsigned*)&Bs[1][n0 + gid][kk + tig * 2 + 8];
            }
            #pragma unroll
            for (int mt = 0; mt < 2; mt++)
                #pragma unroll
                for (int nt = 0; nt < 8; nt++) {
                    mma16816(acc[mt][nt], ah[mt], bh[nt]);   // hi*hi
                    mma16816(acc[mt][nt], ah[mt], bl[nt]);   // hi*lo
                    mma16816(acc[mt][nt], al[mt], bh[nt]);   // lo*hi
                }
        }
        __syncthreads();
    }

    // ---- epilogue ----
    #pragma unroll
    for (int mt = 0; mt < 2; mt++) {
        int r = rb + wm * 32 + mt * 16;
        #pragma unroll
        for (int nt = 0; nt < 8; nt++) {
            int c = cb + wn * 64 + nt * 8 + tig * 2;
            *(float2*)&C[(size_t)(r + gid    ) * N + c] = make_float2(acc[mt][nt][0], acc[mt][nt][1]);
            *(float2*)&C[(size_t)(r + gid + 8) * N + c] = make_float2(acc[mt][nt][2], acc[mt][nt][3]);
        }
    }
}

// ---------------- RoPE in place on [B*Q, nheads*64] ----------------
__global__ void rope_kernel(float* __restrict__ x, const int* __restrict__ pos_ids,
                            const float* __restrict__ cosT, const float* __restrict__ sinT,
                            int nheads, int total) {
    int idx = blockIdx.x * blockDim.x + threadIdx.x;
    if (idx >= total) return;
    int d   = idx & 31;
    int h   = (idx >> 5) % nheads;
    int row = idx / (32 * nheads);
    int pos = pos_ids[row];
    float c1 = cosT[pos * 64 + d],      s1 = sinT[pos * 64 + d];
    float c2 = cosT[pos * 64 + d + 32], s2 = sinT[pos * 64 + d + 32];
    float* p = x + (size_t)row * nheads * 64 + h * 64;
    float x1 = p[d], x2 = p[d + 32];
    p[d]      = x1 * c1 - x2 * s1;
    p[d + 32] = x2 * c2 + x1 * s2;
}

// ---------------- KB selection: qsum over (q, group) ----------------
__global__ void qsum_partial_kernel() {
    int b  = blockIdx.x, ch = blockIdx.y;
    int c  = threadIdx.x;             // 0..511
    int kh = c / CHD, dd = c % CHD;
    float s = 0.f;
    for (int q = ch * 64; q < ch * 64 + 64; q++) {
        const float* row = g_kbq + (size_t)(b * CQ + q) * (CNH * CHD);
        #pragma unroll
        for (int g = 0; g < CG; g++) s += row[(kh * CG + g) * CHD + dd];
    }
    g_qsum_part[(b * 16 + ch) * 512 + c] = s;
}

__global__ void qsum_combine_kernel() {
    int b = blockIdx.x, c = threadIdx.x;
    float s = 0.f;
    #pragma unroll
    for (int ch = 0; ch < 16; ch++) s += g_qsum_part[(b * 16 + ch) * 512 + c];
    g_qsum[b * 512 + c] = s;
}

__global__ void scores_kernel() {
    int gw = blockIdx.x * 8 + (threadIdx.x >> 5);
    int l  = threadIdx.x & 31;
    int b  = gw >> 9, n = gw & 511;
    const float* kr = g_kbk + (size_t)(b * CKB + n) * (CNKV * CHD);
    const float* qs = g_qsum + b * 512;
    float s = 0.f;
    #pragma unroll
    for (int i = l; i < 512; i += 32) s = fmaf(kr[i], qs[i], s);
    #pragma unroll
    for (int o = 16; o > 0; o >>= 1) s += __shfl_xor_sync(0xffffffffu, s, o);
    if (l == 0) g_scores[b * CKB + n] = s;
}

__global__ void topk_kernel() {
    int b = blockIdx.x;
    __shared__ float sv[CKB];
    __shared__ float cv[16];
    __shared__ int   ci[16];
    int tid = threadIdx.x;            // 512 threads
    sv[tid] = g_scores[b * CKB + tid];
    __syncthreads();
    for (int t = 0; t < CTOPK; t++) {
        float v = sv[tid]; int idx = tid;
        #pragma unroll
        for (int o = 16; o > 0; o >>= 1) {
            float ov = __shfl_xor_sync(0xffffffffu, v, o);
            int   oi = __shfl_xor_sync(0xffffffffu, idx, o);
            if (ov > v || (ov == v && oi < idx)) { v = ov; idx = oi; }
        }
        if ((tid & 31) == 0) { cv[tid >> 5] = v; ci[tid >> 5] = idx; }
        __syncthreads();
        if (tid < 32) {
            float v2 = (tid < 16) ? cv[tid] : -3.0e38f;
            int   i2 = (tid < 16) ? ci[tid] : 0x7fffffff;
            #pragma unroll
            for (int o = 16; o > 0; o >>= 1) {
                float ov = __shfl_xor_sync(0xffffffffu, v2, o);
                int   oi = __shfl_xor_sync(0xffffffffu, i2, o);
                if (ov > v2 || (ov == v2 && oi < i2)) { v2 = ov; i2 = oi; }
            }
            if (tid == 0) { g_topidx[b * CTOPK + t] = i2; sv[i2] = -3.0e38f; }
        }
        __syncthreads();
    }
}

// ---------------- fused flash attention: KB(top-100) keys + causal prefix ----------------
__global__ __launch_bounds__(256) void attn_kernel() {
    __shared__ __align__(16) float q_s[32][64];
    __shared__ __align__(16) float kp_s[64 * 66];
    __shared__ __align__(16) float v_s[64][64];

    const int b = blockIdx.z, h = blockIdx.y, qt = blockIdx.x;
    const int kh = h / CG;
    const int tid = threadIdx.x;
    const int w = tid >> 5, l = tid & 31;
    const int q0 = qt * 32;
    const int r0 = w * 4;

    float m[4], lsum[4];
    float2 acc[4];
    #pragma unroll
    for (int r = 0; r < 4; r++) { m[r] = -1e30f; lsum[r] = 0.f; acc[r] = make_float2(0.f, 0.f); }

    for (int ph = 0; ph < 2; ph++) {
        const float* qsrc = ph ? g_q : g_kbq;
        for (int i = tid; i < 32 * 64; i += 256) {
            int r = i >> 6, d = i & 63;
            q_s[r][d] = qsrc[(size_t)(b * CQ + q0 + r) * (CNH * CHD) + h * CHD + d] * SCALE_F;
        }
        __syncthreads();
        const int ntiles = ph ? (q0 + 32 + 63) / 64 : 2;
        for (int t = 0; t < ntiles; t++) {
            if (ph == 0) {
                for (int i = tid; i < 64 * 64; i += 256) {
                    int j = i >> 6, d = i & 63;
                    int kg = t * 64 + j;
                    float kv = 0.f, vv = 0.f;
                    if (kg < CTOPK) {
                        int n = g_topidx[b * CTOPK + kg];
                        size_t base = (size_t)(b * CKB + n) * (CNKV * CHD) + kh * CHD + d;
                        kv = g_kbk[base]; vv = g_kbv[base];
                    }
                    kp_s[d * 66 + j] = kv;
                    v_s[j][d] = vv;
                }
            } else {
                for (int i = tid; i < 64 * 64; i += 256) {
                    int j = i >> 6, d = i & 63;
                    int kg = t * 64 + j;
                    size_t base = (size_t)(b * CQ + kg) * (CNKV * CHD) + kh * CHD + d;
                    kp_s[d * 66 + j] = g_k[base];
                    v_s[j][d] = g_v[base];
                }
            }
            __syncthreads();

            float s[4][2] = {};
            #pragma unroll 16
            for (int d = 0; d < 64; d++) {
                float2 kv = *(const float2*)&kp_s[d * 66 + 2 * l];
                #pragma unroll
                for (int r = 0; r < 4; r++) {
                    float qv = q_s[r0 + r][d];
                    s[r][0] = fmaf(qv, kv.x, s[r][0]);
                    s[r][1] = fmaf(qv, kv.y, s[r][1]);
                }
            }
            const int jg = t * 64 + 2 * l;
            if (ph == 0) {
                #pragma unroll
                for (int r = 0; r < 4; r++) {
                    s[r][0] = (jg     < CTOPK) ? s[r][0] + KB_BIAS : -1e30f;
                    s[r][1] = (jg + 1 < CTOPK) ? s[r][1] + KB_BIAS : -1e30f;
                }
            } else {
                #pragma unroll
                for (int r = 0; r < 4; r++) {
                    int qr = q0 + r0 + r;
                    if (jg     > qr) s[r][0] = -1e30f;
                    if (jg + 1 > qr) s[r][1] = -1e30f;
                }
            }
            float p[4][2];
            #pragma unroll
            for (int r = 0; r < 4; r++) {
                float mx = fmaxf(s[r][0], s[r][1]);
                #pragma unroll
                for (int o = 16; o > 0; o >>= 1) mx = fmaxf(mx, __shfl_xor_sync(0xffffffffu, mx, o));
                float mnew = fmaxf(m[r], mx);
                float corr = __expf(m[r] - mnew);
                p[r][0] = __expf(s[r][0] - mnew);
                p[r][1] = __expf(s[r][1] - mnew);
                float ps = p[r][0] + p[r][1];
                #pragma unroll
                for (int o = 16; o > 0; o >>= 1) ps += __shfl_xor_sync(0xffffffffu, ps, o);
                lsum[r] = lsum[r] * corr + ps;
                acc[r].x *= corr; acc[r].y *= corr;
                m[r] = mnew;
            }
            __syncthreads();
            #pragma unroll
            for (int r = 0; r < 4; r++)
                *(float2*)&kp_s[(r0 + r) * 64 + 2 * l] = make_float2(p[r][0], p[r][1]);
            __syncwarp();
            #pragma unroll 16
            for (int j = 0; j < 64; j++) {
                float2 vv = *(const float2*)&v_s[j][2 * l];
                #pragma unroll
                for (int r = 0; r < 4; r++) {
                    float pj = kp_s[(r0 + r) * 64 + j];
                    acc[r].x = fmaf(pj, vv.x, acc[r].x);
                    acc[r].y = fmaf(pj, vv.y, acc[r].y);
                }
            }
            __syncthreads();
        }
    }
    #pragma unroll
    for (int r = 0; r < 4; r++) {
        float inv = 1.f / lsum[r];
        float2 o = make_float2(acc[r].x * inv, acc[r].y * inv);
        *(float2*)&g_attn[(size_t)(b * CQ + q0 + r0 + r) * (CNH * CHD) + h * CHD + 2 * l] = o;
    }
}

// ---------------- launch ----------------
extern "C" void kernel_launch(void* const* d_in, const int* in_sizes, int n_in,
                              void* d_out, int out_size) {
    const float* hs   = (const float*)d_in[0];
    const float* kb   = (const float*)d_in[1];
    const float* Wq   = (const float*)d_in[2];
    const float* Wk   = (const float*)d_in[3];
    const float* Wv   = (const float*)d_in[4];
    const float* Wo   = (const float*)d_in[5];
    const float* Wqn  = (const float*)d_in[6];
    const float* Wkbk = (const float*)d_in[7];
    const float* Wkbv = (const float*)d_in[8];
    const float* cosT = (const float*)d_in[9];
    const float* sinT = (const float*)d_in[10];
    const int*   pos  = (const int*)d_in[12];
    float* out = (float*)d_out;

    float *pq, *pkbq, *pk, *pv, *pkbk, *pkbv, *pattn;
    cudaGetSymbolAddress((void**)&pq,    g_q);
    cudaGetSymbolAddress((void**)&pkbq,  g_kbq);
    cudaGetSymbolAddress((void**)&pk,    g_k);
    cudaGetSymbolAddress((void**)&pv,    g_v);
    cudaGetSymbolAddress((void**)&pkbk,  g_kbk);
    cudaGetSymbolAddress((void**)&pkbv,  g_kbv);
    cudaGetSymbolAddress((void**)&pattn, g_attn);

    const int M = CB * CQ;          // 2048
    // projections (tensor-core bf16-split GEMMs)
    gemm_bf16x3_kernel<<<dim3(CHID/128, M/128), 256>>>(hs,  Wq,   pq,   M, CHID, CHID);
    gemm_bf16x3_kernel<<<dim3(CHID/128, M/128), 256>>>(hs,  Wqn,  pkbq, M, CHID, CHID);
    gemm_bf16x3_kernel<<<dim3(512/128,  M/128), 256>>>(hs,  Wk,   pk,   M, 512,  CHID);
    gemm_bf16x3_kernel<<<dim3(512/128,  M/128), 256>>>(hs,  Wv,   pv,   M, 512,  CHID);
    gemm_bf16x3_kernel<<<dim3(512/128, (CB*CKB)/128), 256>>>(kb, Wkbk, pkbk, CB*CKB, 512, CHID);
    gemm_bf16x3_kernel<<<dim3(512/128, (CB*CKB)/128), 256>>>(kb, Wkbv, pkbv, CB*CKB, 512, CHID);
    // RoPE
    {
        int tq = CB * CQ * CNH * 32;
        rope_kernel<<<(tq + 255) / 256, 256>>>(pq, pos, cosT, sinT, CNH, tq);
        int tk = CB * CQ * CNKV * 32;
        rope_kernel<<<(tk + 255) / 256, 256>>>(pk, pos, cosT, sinT, CNKV, tk);
    }
    // KB top-k selection
    qsum_partial_kernel<<<dim3(CB, 16), 512>>>();
    qsum_combine_kernel<<<CB, 512>>>();
    scores_kernel<<<(CB * CKB) / 8, 256>>>();
    topk_kernel<<<CB, 512>>>();
    // fused attention
    attn_kernel<<<dim3(CQ / 32, CNH, CB), 256>>>();
    // output projection
    gemm_bf16x3_kernel<<<dim3(CHID/128, M/128), 256>>>(pattn, Wo, out, M, CHID, CHID);
}

// round 3
// speedup vs baseline: 2.4432x; 2.4432x over previous
#include <cuda_runtime.h>
#include <cuda_bf16.h>
#include <math.h>
#include <stdint.h>

// ---------------- problem constants ----------------
constexpr int CB    = 2;
constexpr int CQ    = 1024;
constexpr int CHID  = 2048;
constexpr int CNH   = 32;
constexpr int CNKV  = 8;
constexpr int CHD   = 64;
constexpr int CG    = 4;
constexpr int CKB   = 512;
constexpr int CTOPK = 100;
#define SCALE_F  0.125f
#define KB_BIAS  1.6331544f

// ---------------- fp32 scratch ----------------
__device__ float g_q   [CB*CQ*CNH*CHD];        // roped Q [B,Q,NH*HD]
__device__ float g_kbq [CB*CQ*CNH*CHD];        // KB query (no rope)
__device__ float g_kv  [CB*CQ*1024];           // [row][ k(512) | v(512) ]
__device__ float g_kbkv[CB*CKB*1024];          // [row][ kbk(512) | kbv(512) ]
__device__ float g_attn[CB*CQ*CNH*CHD];
__device__ float g_qsum_part[CB*16*CNKV*CHD];
__device__ float g_qsum[CB*CNKV*CHD];
__device__ float g_scores[CB*CKB];
__device__ int   g_topidx[CB*CTOPK];

// ---------------- bf16 hi/lo split buffers ----------------
__device__ __nv_bfloat16 s_hs_h [CB*CQ*CHID],  s_hs_l [CB*CQ*CHID];
__device__ __nv_bfloat16 s_kb_h [CB*CKB*CHID], s_kb_l [CB*CKB*CHID];
__device__ __nv_bfloat16 s_at_h [CB*CQ*CHID],  s_at_l [CB*CQ*CHID];
__device__ __nv_bfloat16 s_wq_h [CHID*CHID],   s_wq_l [CHID*CHID];
__device__ __nv_bfloat16 s_wqn_h[CHID*CHID],   s_wqn_l[CHID*CHID];
__device__ __nv_bfloat16 s_wo_h [CHID*CHID],   s_wo_l [CHID*CHID];
__device__ __nv_bfloat16 s_wkv_h[CHID*1024],   s_wkv_l[CHID*1024];   // [K][ Wk | Wv ]
__device__ __nv_bfloat16 s_wkb_h[CHID*1024],   s_wkb_l[CHID*1024];   // [K][ Wkbk | Wkbv ]

// ---------------- split: f32 -> bf16 hi + bf16 lo (optionally strided output) ----------------
__global__ void split_kernel(const float* __restrict__ in,
                             __nv_bfloat16* __restrict__ oh, __nv_bfloat16* __restrict__ ol,
                             int cols, int ostride, int coff, int total4) {
    int i = blockIdx.x * blockDim.x + threadIdx.x;
    if (i >= total4) return;
    int c4pr = cols >> 2;
    int r = i / c4pr, c4 = i % c4pr;
    float4 v = ((const float4*)in)[i];
    float vv[4] = {v.x, v.y, v.z, v.w};
    __nv_bfloat16 h[4], l[4];
    #pragma unroll
    for (int j = 0; j < 4; j++) {
        h[j] = __float2bfloat16_rn(vv[j]);
        l[j] = __float2bfloat16_rn(vv[j] - __bfloat162float(h[j]));
    }
    size_t ob = (size_t)r * ostride + coff + c4 * 4;
    *(__nv_bfloat162*)&oh[ob]     = __nv_bfloat162(h[0], h[1]);
    *(__nv_bfloat162*)&oh[ob + 2] = __nv_bfloat162(h[2], h[3]);
    *(__nv_bfloat162*)&ol[ob]     = __nv_bfloat162(l[0], l[1]);
    *(__nv_bfloat162*)&ol[ob + 2] = __nv_bfloat162(l[2], l[3]);
}

// ---------------- tensor-core GEMM (bf16 hi/lo, 3-pass, cp.async 3-stage, ldmatrix) ----------------
constexpr int GBM = 128, GBN = 128, GBK = 32, GSTG = 3;
constexpr int STAGE_BYTES = 32768;   // Ah 8K | Al 8K | Bh 8K | Bl 8K

__device__ __forceinline__ void cp_async16(uint32_t dst, const void* src) {
    asm volatile("cp.async.cg.shared.global [%0], [%1], 16;\n" :: "r"(dst), "l"(src));
}
__device__ __forceinline__ void mma16816(float* c, const unsigned* a, const unsigned* b) {
    asm volatile(
        "mma.sync.aligned.m16n8k16.row.col.f32.bf16.bf16.f32 "
        "{%0,%1,%2,%3}, {%4,%5,%6,%7}, {%8,%9}, {%0,%1,%2,%3};"
        : "+f"(c[0]), "+f"(c[1]), "+f"(c[2]), "+f"(c[3])
        : "r"(a[0]), "r"(a[1]), "r"(a[2]), "r"(a[3]), "r"(b[0]), "r"(b[1]));
}

__device__ __forceinline__ void gemm_issue_stage(
        uint32_t base, int tid,
        const __nv_bfloat16* Ah, const __nv_bfloat16* Al,
        const __nv_bfloat16* Bh, const __nv_bfloat16* Bl,
        int rb, int cb, int k0, int K, int N) {
    // A: 128 rows x 4 chunks (16B) per precision
    #pragma unroll
    for (int it = 0; it < 2; it++) {
        int i = tid + it * 256;
        int r = i >> 2, c = i & 3;
        uint32_t dst = base + r * 64 + (((c ^ ((r >> 1) & 3))) << 4);
        size_t so = (size_t)(rb + r) * K + k0 + c * 8;
        cp_async16(dst,        Ah + so);
        cp_async16(dst + 8192, Al + so);
    }
    // B: 32 rows x 16 chunks per precision
    #pragma unroll
    for (int it = 0; it < 2; it++) {
        int i = tid + it * 256;
        int r = i >> 4, cn = i & 15;
        uint32_t dst = base + 16384 + r * 256 + (((cn ^ (r & 7))) << 4);
        size_t so = (size_t)(k0 + r) * N + cb + cn * 8;
        cp_async16(dst,        Bh + so);
        cp_async16(dst + 8192, Bl + so);
    }
}

__global__ __launch_bounds__(256)
void gemm_bf16tc(const __nv_bfloat16* __restrict__ Ah, const __nv_bfloat16* __restrict__ Al,
                 const __nv_bfloat16* __restrict__ Bh, const __nv_bfloat16* __restrict__ Bl,
                 float* __restrict__ C, int M, int N, int K) {
    extern __shared__ char smem[];
    uint32_t sb = (uint32_t)__cvta_generic_to_shared(smem);
    const int tid = threadIdx.x, lane = tid & 31, wid = tid >> 5;
    const int wm = wid >> 1, wn = wid & 1;
    const int gid = lane >> 2, tig = lane & 3;
    const int rb = blockIdx.y * GBM, cb = blockIdx.x * GBN;

    float acc[2][8][4];
    #pragma unroll
    for (int mt = 0; mt < 2; mt++)
        #pragma unroll
        for (int nt = 0; nt < 8; nt++)
            #pragma unroll
            for (int i = 0; i < 4; i++) acc[mt][nt][i] = 0.f;

    const int nk = K / GBK;
    gemm_issue_stage(sb, tid, Ah, Al, Bh, Bl, rb, cb, 0, K, N);
    asm volatile("cp.async.commit_group;\n" ::);
    if (nk > 1) {
        gemm_issue_stage(sb + STAGE_BYTES, tid, Ah, Al, Bh, Bl, rb, cb, GBK, K, N);
    }
    asm volatile("cp.async.commit_group;\n" ::);

    // ldmatrix lane-address components
    const int sub = lane >> 3, li = lane & 7;
    const int arow_off = ((sub & 1) ? 8 : 0) + li;   // + r0
    const int akc_off  = (sub >> 1) ? 8 : 0;         // + kk
    const int bk_off   = ((sub & 1) ? 8 : 0) + li;   // + kk
    const int bn_off   = (sub >> 1) ? 8 : 0;         // + n0

    for (int i = 0; i < nk; i++) {
        asm volatile("cp.async.wait_group 1;\n" ::);
        __syncthreads();
        const int st = i % GSTG;
        const uint32_t abase = sb + st * STAGE_BYTES;
        const uint32_t bbase = abase + 16384;
        if (i + 2 < nk)
            gemm_issue_stage(sb + ((i + 2) % GSTG) * STAGE_BYTES, tid,
                             Ah, Al, Bh, Bl, rb, cb, (i + 2) * GBK, K, N);
        asm volatile("cp.async.commit_group;\n" ::);

        #pragma unroll
        for (int kk = 0; kk < GBK; kk += 16) {
            // ---- B fragments (4 x ldmatrix.x4.trans per precision) ----
            unsigned bh[8][2], bl[8][2];
            #pragma unroll
            for (int np = 0; np < 4; np++) {
                int n0 = wn * 64 + np * 16;
                int k  = kk + bk_off;
                int n  = n0 + bn_off;
                uint32_t addr = bbase + k * 256 + ((((n >> 3) ^ (k & 7))) << 4);
                unsigned r0, r1, r2, r3;
                asm volatile("ldmatrix.sync.aligned.m8n8.x4.trans.shared.b16 {%0,%1,%2,%3}, [%4];"
                    : "=r"(r0), "=r"(r1), "=r"(r2), "=r"(r3) : "r"(addr));
                bh[np*2][0] = r0; bh[np*2][1] = r1; bh[np*2+1][0] = r2; bh[np*2+1][1] = r3;
                asm volatile("ldmatrix.sync.aligned.m8n8.x4.trans.shared.b16 {%0,%1,%2,%3}, [%4];"
                    : "=r"(r0), "=r"(r1), "=r"(r2), "=r"(r3) : "r"(addr + 8192));
                bl[np*2][0] = r0; bl[np*2][1] = r1; bl[np*2+1][0] = r2; bl[np*2+1][1] = r3;
            }
            // ---- per m16 tile: A fragments + 24 MMAs ----
            #pragma unroll
            for (int mt = 0; mt < 2; mt++) {
                int r0 = wm * 32 + mt * 16;
                int row  = r0 + arow_off;
                int kcol = kk + akc_off;
                uint32_t aaddr = abase + row * 64 + ((((kcol >> 3) ^ ((row >> 1) & 3))) << 4);
                unsigned ah[4], al[4];
                asm volatile("ldmatrix.sync.aligned.m8n8.x4.shared.b16 {%0,%1,%2,%3}, [%4];"
                    : "=r"(ah[0]), "=r"(ah[1]), "=r"(ah[2]), "=r"(ah[3]) : "r"(aaddr));
                asm volatile("ldmatrix.sync.aligned.m8n8.x4.shared.b16 {%0,%1,%2,%3}, [%4];"
                    : "=r"(al[0]), "=r"(al[1]), "=r"(al[2]), "=r"(al[3]) : "r"(aaddr + 8192));
                #pragma unroll
                for (int nt = 0; nt < 8; nt++) {
                    mma16816(acc[mt][nt], ah, bh[nt]);
                    mma16816(acc[mt][nt], ah, bl[nt]);
                    mma16816(acc[mt][nt], al, bh[nt]);
                }
            }
        }
        __syncthreads();
    }

    // ---- epilogue ----
    #pragma unroll
    for (int mt = 0; mt < 2; mt++) {
        int r = rb + wm * 32 + mt * 16;
        #pragma unroll
        for (int nt = 0; nt < 8; nt++) {
            int c = cb + wn * 64 + nt * 8 + tig * 2;
            *(float2*)&C[(size_t)(r + gid    ) * N + c] = make_float2(acc[mt][nt][0], acc[mt][nt][1]);
            *(float2*)&C[(size_t)(r + gid + 8) * N + c] = make_float2(acc[mt][nt][2], acc[mt][nt][3]);
        }
    }
}

// ---------------- RoPE in place; row layout [row][row_stride], heads at h*64 ----------------
__global__ void rope_kernel(float* __restrict__ x, const int* __restrict__ pos_ids,
                            const float* __restrict__ cosT, const float* __restrict__ sinT,
                            int nheads, int row_stride, int total) {
    int idx = blockIdx.x * blockDim.x + threadIdx.x;
    if (idx >= total) return;
    int d   = idx & 31;
    int h   = (idx >> 5) % nheads;
    int row = idx / (32 * nheads);
    int pos = pos_ids[row];
    float c1 = cosT[pos * 64 + d],      s1 = sinT[pos * 64 + d];
    float c2 = cosT[pos * 64 + d + 32], s2 = sinT[pos * 64 + d + 32];
    float* p = x + (size_t)row * row_stride + h * 64;
    float x1 = p[d], x2 = p[d + 32];
    p[d]      = x1 * c1 - x2 * s1;
    p[d + 32] = x2 * c2 + x1 * s2;
}

// ---------------- KB selection ----------------
__global__ void qsum_partial_kernel() {
    int b  = blockIdx.x, ch = blockIdx.y;
    int c  = threadIdx.x;
    int kh = c / CHD, dd = c % CHD;
    float s = 0.f;
    for (int q = ch * 64; q < ch * 64 + 64; q++) {
        const float* row = g_kbq + (size_t)(b * CQ + q) * (CNH * CHD);
        #pragma unroll
        for (int g = 0; g < CG; g++) s += row[(kh * CG + g) * CHD + dd];
    }
    g_qsum_part[(b * 16 + ch) * 512 + c] = s;
}

__global__ void qsum_combine_kernel() {
    int b = blockIdx.x, c = threadIdx.x;
    float s = 0.f;
    #pragma unroll
    for (int ch = 0; ch < 16; ch++) s += g_qsum_part[(b * 16 + ch) * 512 + c];
    g_qsum[b * 512 + c] = s;
}

__global__ void scores_kernel() {
    int gw = blockIdx.x * 8 + (threadIdx.x >> 5);
    int l  = threadIdx.x & 31;
    int b  = gw >> 9, n = gw & 511;
    const float* kr = g_kbkv + (size_t)(b * CKB + n) * 1024;   // k half
    const float* qs = g_qsum + b * 512;
    float s = 0.f;
    #pragma unroll
    for (int i = l; i < 512; i += 32) s = fmaf(kr[i], qs[i], s);
    #pragma unroll
    for (int o = 16; o > 0; o >>= 1) s += __shfl_xor_sync(0xffffffffu, s, o);
    if (l == 0) g_scores[b * CKB + n] = s;
}

__global__ void topk_kernel() {
    int b = blockIdx.x;
    __shared__ float sv[CKB];
    __shared__ float cv[16];
    __shared__ int   ci[16];
    int tid = threadIdx.x;
    sv[tid] = g_scores[b * CKB + tid];
    __syncthreads();
    for (int t = 0; t < CTOPK; t++) {
        float v = sv[tid]; int idx = tid;
        #pragma unroll
        for (int o = 16; o > 0; o >>= 1) {
            float ov = __shfl_xor_sync(0xffffffffu, v, o);
            int   oi = __shfl_xor_sync(0xffffffffu, idx, o);
            if (ov > v || (ov == v && oi < idx)) { v = ov; idx = oi; }
        }
        if ((tid & 31) == 0) { cv[tid >> 5] = v; ci[tid >> 5] = idx; }
        __syncthreads();
        if (tid < 32) {
            float v2 = (tid < 16) ? cv[tid] : -3.0e38f;
            int   i2 = (tid < 16) ? ci[tid] : 0x7fffffff;
            #pragma unroll
            for (int o = 16; o > 0; o >>= 1) {
                float ov = __shfl_xor_sync(0xffffffffu, v2, o);
                int   oi = __shfl_xor_sync(0xffffffffu, i2, o);
                if (ov > v2 || (ov == v2 && oi < i2)) { v2 = ov; i2 = oi; }
            }
            if (tid == 0) { g_topidx[b * CTOPK + t] = i2; sv[i2] = -3.0e38f; }
        }
        __syncthreads();
    }
}

// ---------------- fused flash attention ----------------
__global__ __launch_bounds__(256) void attn_kernel() {
    __shared__ __align__(16) float q_s[32][64];
    __shared__ __align__(16) float kp_s[64 * 66];
    __shared__ __align__(16) float v_s[64][64];

    const int b = blockIdx.z, h = blockIdx.y, qt = blockIdx.x;
    const int kh = h / CG;
    const int tid = threadIdx.x;
    const int w = tid >> 5, l = tid & 31;
    const int q0 = qt * 32;
    const int r0 = w * 4;

    float m[4], lsum[4];
    float2 acc[4];
    #pragma unroll
    for (int r = 0; r < 4; r++) { m[r] = -1e30f; lsum[r] = 0.f; acc[r] = make_float2(0.f, 0.f); }

    for (int ph = 0; ph < 2; ph++) {
        const float* qsrc = ph ? g_q : g_kbq;
        for (int i = tid; i < 32 * 64; i += 256) {
            int r = i >> 6, d = i & 63;
            q_s[r][d] = qsrc[(size_t)(b * CQ + q0 + r) * (CNH * CHD) + h * CHD + d] * SCALE_F;
        }
        __syncthreads();
        const int ntiles = ph ? (q0 + 32 + 63) / 64 : 2;
        for (int t = 0; t < ntiles; t++) {
            if (ph == 0) {
                for (int i = tid; i < 64 * 64; i += 256) {
                    int j = i >> 6, d = i & 63;
                    int kg = t * 64 + j;
                    float kv = 0.f, vv = 0.f;
                    if (kg < CTOPK) {
                        int n = g_topidx[b * CTOPK + kg];
                        size_t base = (size_t)(b * CKB + n) * 1024 + kh * CHD + d;
                        kv = g_kbkv[base]; vv = g_kbkv[base + 512];
                    }
                    kp_s[d * 66 + j] = kv;
                    v_s[j][d] = vv;
                }
            } else {
                for (int i = tid; i < 64 * 64; i += 256) {
                    int j = i >> 6, d = i & 63;
                    int kg = t * 64 + j;
                    size_t base = (size_t)(b * CQ + kg) * 1024 + kh * CHD + d;
                    kp_s[d * 66 + j] = g_kv[base];
                    v_s[j][d] = g_kv[base + 512];
                }
            }
            __syncthreads();

            float s[4][2] = {};
            #pragma unroll 16
            for (int d = 0; d < 64; d++) {
                float2 kv = *(const float2*)&kp_s[d * 66 + 2 * l];
                #pragma unroll
                for (int r = 0; r < 4; r++) {
                    float qv = q_s[r0 + r][d];
                    s[r][0] = fmaf(qv, kv.x, s[r][0]);
                    s[r][1] = fmaf(qv, kv.y, s[r][1]);
                }
            }
            const int jg = t * 64 + 2 * l;
            if (ph == 0) {
                #pragma unroll
                for (int r = 0; r < 4; r++) {
                    s[r][0] = (jg     < CTOPK) ? s[r][0] + KB_BIAS : -1e30f;
                    s[r][1] = (jg + 1 < CTOPK) ? s[r][1] + KB_BIAS : -1e30f;
                }
            } else {
                #pragma unroll
                for (int r = 0; r < 4; r++) {
                    int qr = q0 + r0 + r;
                    if (jg     > qr) s[r][0] = -1e30f;
                    if (jg + 1 > qr) s[r][1] = -1e30f;
                }
            }
            float p[4][2];
            #pragma unroll
            for (int r = 0; r < 4; r++) {
                float mx = fmaxf(s[r][0], s[r][1]);
                #pragma unroll
                for (int o = 16; o > 0; o >>= 1) mx = fmaxf(mx, __shfl_xor_sync(0xffffffffu, mx, o));
                float mnew = fmaxf(m[r], mx);
                float corr = __expf(m[r] - mnew);
                p[r][0] = __expf(s[r][0] - mnew);
                p[r][1] = __expf(s[r][1] - mnew);
                float ps = p[r][0] + p[r][1];
                #pragma unroll
                for (int o = 16; o > 0; o >>= 1) ps += __shfl_xor_sync(0xffffffffu, ps, o);
                lsum[r] = lsum[r] * corr + ps;
                acc[r].x *= corr; acc[r].y *= corr;
                m[r] = mnew;
            }
            __syncthreads();
            #pragma unroll
            for (int r = 0; r < 4; r++)
                *(float2*)&kp_s[(r0 + r) * 64 + 2 * l] = make_float2(p[r][0], p[r][1]);
            __syncwarp();
            #pragma unroll 16
            for (int j = 0; j < 64; j++) {
                float2 vv = *(const float2*)&v_s[j][2 * l];
                #pragma unroll
                for (int r = 0; r < 4; r++) {
                    float pj = kp_s[(r0 + r) * 64 + j];
                    acc[r].x = fmaf(pj, vv.x, acc[r].x);
                    acc[r].y = fmaf(pj, vv.y, acc[r].y);
                }
            }
            __syncthreads();
        }
    }
    #pragma unroll
    for (int r = 0; r < 4; r++) {
        float inv = 1.f / lsum[r];
        float2 o = make_float2(acc[r].x * inv, acc[r].y * inv);
        *(float2*)&g_attn[(size_t)(b * CQ + q0 + r0 + r) * (CNH * CHD) + h * CHD + 2 * l] = o;
    }
}

// ---------------- launch ----------------
static inline void launch_split(const float* in, __nv_bfloat16* oh, __nv_bfloat16* ol,
                                int rows, int cols, int ostride, int coff) {
    int total4 = rows * cols / 4;
    split_kernel<<<(total4 + 255) / 256, 256>>>(in, oh, ol, cols, ostride, coff, total4);
}

extern "C" void kernel_launch(void* const* d_in, const int* in_sizes, int n_in,
                              void* d_out, int out_size) {
    const float* hs   = (const float*)d_in[0];
    const float* kb   = (const float*)d_in[1];
    const float* Wq   = (const float*)d_in[2];
    const float* Wk   = (const float*)d_in[3];
    const float* Wv   = (const float*)d_in[4];
    const float* Wo   = (const float*)d_in[5];
    const float* Wqn  = (const float*)d_in[6];
    const float* Wkbk = (const float*)d_in[7];
    const float* Wkbv = (const float*)d_in[8];
    const float* cosT = (const float*)d_in[9];
    const float* sinT = (const float*)d_in[10];
    const int*   pos  = (const int*)d_in[12];
    float* out = (float*)d_out;

    float *pq, *pkbq, *pkv, *pkbkv, *pattn;
    cudaGetSymbolAddress((void**)&pq,    g_q);
    cudaGetSymbolAddress((void**)&pkbq,  g_kbq);
    cudaGetSymbolAddress((void**)&pkv,   g_kv);
    cudaGetSymbolAddress((void**)&pkbkv, g_kbkv);
    cudaGetSymbolAddress((void**)&pattn, g_attn);

    __nv_bfloat16 *hs_h, *hs_l, *kb_h, *kb_l, *at_h, *at_l;
    __nv_bfloat16 *wq_h, *wq_l, *wqn_h, *wqn_l, *wo_h, *wo_l, *wkv_h, *wkv_l, *wkb_h, *wkb_l;
    cudaGetSymbolAddress((void**)&hs_h,  s_hs_h);  cudaGetSymbolAddress((void**)&hs_l,  s_hs_l);
    cudaGetSymbolAddress((void**)&kb_h,  s_kb_h);  cudaGetSymbolAddress((void**)&kb_l,  s_kb_l);
    cudaGetSymbolAddress((void**)&at_h,  s_at_h);  cudaGetSymbolAddress((void**)&at_l,  s_at_l);
    cudaGetSymbolAddress((void**)&wq_h,  s_wq_h);  cudaGetSymbolAddress((void**)&wq_l,  s_wq_l);
    cudaGetSymbolAddress((void**)&wqn_h, s_wqn_h); cudaGetSymbolAddress((void**)&wqn_l, s_wqn_l);
    cudaGetSymbolAddress((void**)&wo_h,  s_wo_h);  cudaGetSymbolAddress((void**)&wo_l,  s_wo_l);
    cudaGetSymbolAddress((void**)&wkv_h, s_wkv_h); cudaGetSymbolAddress((void**)&wkv_l, s_wkv_l);
    cudaGetSymbolAddress((void**)&wkb_h, s_wkb_h); cudaGetSymbolAddress((void**)&wkb_l, s_wkb_l);

    static int smem_set = 0;
    if (!smem_set) {
        cudaFuncSetAttribute(gemm_bf16tc, cudaFuncAttributeMaxDynamicSharedMemorySize,
                             GSTG * STAGE_BYTES);
        smem_set = 1;
    }

    const int M = CB * CQ;   // 2048

    // ---- split conversions ----
    launch_split(hs,   hs_h,  hs_l,  M,        CHID, CHID, 0);
    launch_split(kb,   kb_h,  kb_l,  CB*CKB,   CHID, CHID, 0);
    launch_split(Wq,   wq_h,  wq_l,  CHID,     CHID, CHID, 0);
    launch_split(Wqn,  wqn_h, wqn_l, CHID,     CHID, CHID, 0);
    launch_split(Wo,   wo_h,  wo_l,  CHID,     CHID, CHID, 0);
    launch_split(Wk,   wkv_h, wkv_l, CHID,     512,  1024, 0);
    launch_split(Wv,   wkv_h, wkv_l, CHID,     512,  1024, 512);
    launch_split(Wkbk, wkb_h, wkb_l, CHID,     512,  1024, 0);
    launch_split(Wkbv, wkb_h, wkb_l, CHID,     512,  1024, 512);

    const int SMEM = GSTG * STAGE_BYTES;
    // ---- projections ----
    gemm_bf16tc<<<dim3(CHID/GBN, M/GBM), 256, SMEM>>>(hs_h, hs_l, wq_h,  wq_l,  pq,    M, CHID, CHID);
    gemm_bf16tc<<<dim3(CHID/GBN, M/GBM), 256, SMEM>>>(hs_h, hs_l, wqn_h, wqn_l, pkbq,  M, CHID, CHID);
    gemm_bf16tc<<<dim3(1024/GBN, M/GBM), 256, SMEM>>>(hs_h, hs_l, wkv_h, wkv_l, pkv,   M, 1024, CHID);
    gemm_bf16tc<<<dim3(1024/GBN, (CB*CKB)/GBM), 256, SMEM>>>(kb_h, kb_l, wkb_h, wkb_l, pkbkv, CB*CKB, 1024, CHID);

    // ---- RoPE ----
    {
        int tq = CB * CQ * CNH * 32;
        rope_kernel<<<(tq + 255) / 256, 256>>>(pq, pos, cosT, sinT, CNH, CNH*CHD, tq);
        int tk = CB * CQ * CNKV * 32;
        rope_kernel<<<(tk + 255) / 256, 256>>>(pkv, pos, cosT, sinT, CNKV, 1024, tk);
    }
    // ---- KB top-k ----
    qsum_partial_kernel<<<dim3(CB, 16), 512>>>();
    qsum_combine_kernel<<<CB, 512>>>();
    scores_kernel<<<(CB * CKB) / 8, 256>>>();
    topk_kernel<<<CB, 512>>>();
    // ---- attention ----
    attn_kernel<<<dim3(CQ / 32, CNH, CB), 256>>>();
    // ---- output projection ----
    launch_split(pattn, at_h, at_l, M, CHID, CHID, 0);
    gemm_bf16tc<<<dim3(CHID/GBN, M/GBM), 256, SMEM>>>(at_h, at_l, wo_h, wo_l, out, M, CHID, CHID);
}

// round 4
// speedup vs baseline: 3.4511x; 1.4126x over previous
#include <cuda_runtime.h>
#include <cuda_bf16.h>
#include <math.h>
#include <stdint.h>

// ---------------- problem constants ----------------
constexpr int CB    = 2;
constexpr int CQ    = 1024;
constexpr int CHID  = 2048;
constexpr int CNH   = 32;
constexpr int CNKV  = 8;
constexpr int CHD   = 64;
constexpr int CG    = 4;
constexpr int CKB   = 512;
constexpr int CTOPK = 100;
#define SCALE_L2E 0.18033688f     // 0.125 * log2(e)
#define KB_B2     2.3561430f      // log2(512/100)

// ---------------- fp32 scratch ----------------
__device__ float g_q   [CB*CQ*CNH*CHD];        // roped Q
__device__ float g_kbq [CB*CQ*CNH*CHD];        // KB query (no rope)
__device__ float g_kv  [CB*CQ*1024];           // [row][ k(512) | v(512) ]
__device__ float g_kbkv[CB*CKB*1024];          // [row][ kbk | kbv ]
__device__ float g_qsum_part[CB*16*CNKV*CHD];
__device__ float g_qsum[CB*CNKV*CHD];
__device__ float g_scores[CB*CKB];
__device__ int   g_topidx[CB*CTOPK];

// ---------------- bf16 hi/lo split buffers ----------------
__device__ __nv_bfloat16 s_hs_h [CB*CQ*CHID],  s_hs_l [CB*CQ*CHID];
__device__ __nv_bfloat16 s_kb_h [CB*CKB*CHID], s_kb_l [CB*CKB*CHID];
__device__ __nv_bfloat16 s_at_h [CB*CQ*CHID],  s_at_l [CB*CQ*CHID];
__device__ __nv_bfloat16 s_wq_h [CHID*CHID],   s_wq_l [CHID*CHID];
__device__ __nv_bfloat16 s_wqn_h[CHID*CHID],   s_wqn_l[CHID*CHID];
__device__ __nv_bfloat16 s_wo_h [CHID*CHID],   s_wo_l [CHID*CHID];
__device__ __nv_bfloat16 s_wkv_h[CHID*1024],   s_wkv_l[CHID*1024];
__device__ __nv_bfloat16 s_wkb_h[CHID*1024],   s_wkb_l[CHID*1024];
// attention operands (pre-scaled Q in log2 units)
__device__ __nv_bfloat16 s_qh  [CB*CQ*CHID],   s_ql  [CB*CQ*CHID];
__device__ __nv_bfloat16 s_kbqh[CB*CQ*CHID],   s_kbql[CB*CQ*CHID];
__device__ __nv_bfloat16 s_kvh [CB*CQ*1024],   s_kvl [CB*CQ*1024];
__device__ __nv_bfloat16 s_kbkvh[CB*CKB*1024], s_kbkvl[CB*CKB*1024];

// ---------------- split: f32*scale -> bf16 hi + lo ----------------
__global__ void split_kernel(const float* __restrict__ in,
                             __nv_bfloat16* __restrict__ oh, __nv_bfloat16* __restrict__ ol,
                             int cols, int ostride, int coff, float scale, int total4) {
    int i = blockIdx.x * blockDim.x + threadIdx.x;
    if (i >= total4) return;
    int c4pr = cols >> 2;
    int r = i / c4pr, c4 = i % c4pr;
    float4 v = ((const float4*)in)[i];
    float vv[4] = {v.x * scale, v.y * scale, v.z * scale, v.w * scale};
    __nv_bfloat16 h[4], l[4];
    #pragma unroll
    for (int j = 0; j < 4; j++) {
        h[j] = __float2bfloat16_rn(vv[j]);
        l[j] = __float2bfloat16_rn(vv[j] - __bfloat162float(h[j]));
    }
    size_t ob = (size_t)r * ostride + coff + c4 * 4;
    *(__nv_bfloat162*)&oh[ob]     = __nv_bfloat162(h[0], h[1]);
    *(__nv_bfloat162*)&oh[ob + 2] = __nv_bfloat162(h[2], h[3]);
    *(__nv_bfloat162*)&ol[ob]     = __nv_bfloat162(l[0], l[1]);
    *(__nv_bfloat162*)&ol[ob + 2] = __nv_bfloat162(l[2], l[3]);
}

// ---------------- common PTX helpers ----------------
__device__ __forceinline__ void cp_async16(uint32_t dst, const void* src) {
    asm volatile("cp.async.cg.shared.global [%0], [%1], 16;\n" :: "r"(dst), "l"(src));
}
__device__ __forceinline__ void mma16816(float* c, const unsigned* a, const unsigned* b) {
    asm volatile(
        "mma.sync.aligned.m16n8k16.row.col.f32.bf16.bf16.f32 "
        "{%0,%1,%2,%3}, {%4,%5,%6,%7}, {%8,%9}, {%0,%1,%2,%3};"
        : "+f"(c[0]), "+f"(c[1]), "+f"(c[2]), "+f"(c[3])
        : "r"(a[0]), "r"(a[1]), "r"(a[2]), "r"(a[3]), "r"(b[0]), "r"(b[1]));
}
#define LDSM4(R, addr) asm volatile( \
    "ldmatrix.sync.aligned.m8n8.x4.shared.b16 {%0,%1,%2,%3}, [%4];" \
    : "=r"((R)[0]), "=r"((R)[1]), "=r"((R)[2]), "=r"((R)[3]) : "r"(addr))
#define LDSM4T(R, addr) asm volatile( \
    "ldmatrix.sync.aligned.m8n8.x4.trans.shared.b16 {%0,%1,%2,%3}, [%4];" \
    : "=r"((R)[0]), "=r"((R)[1]), "=r"((R)[2]), "=r"((R)[3]) : "r"(addr))
__device__ __forceinline__ float fexp2(float x) {
    float y; asm("ex2.approx.ftz.f32 %0, %1;" : "=f"(y) : "f"(x)); return y;
}

// ---------------- tensor-core GEMM (bf16 hi/lo, 3-pass, cp.async 3-stage, ldmatrix) ----------------
constexpr int GBM = 128, GBN = 128, GBK = 32, GSTG = 3;
constexpr int STAGE_BYTES = 32768;

__device__ __forceinline__ void gemm_issue_stage(
        uint32_t base, int tid,
        const __nv_bfloat16* Ah, const __nv_bfloat16* Al,
        const __nv_bfloat16* Bh, const __nv_bfloat16* Bl,
        int rb, int cb, int k0, int K, int N) {
    #pragma unroll
    for (int it = 0; it < 2; it++) {
        int i = tid + it * 256;
        int r = i >> 2, c = i & 3;
        uint32_t dst = base + r * 64 + (((c ^ ((r >> 1) & 3))) << 4);
        size_t so = (size_t)(rb + r) * K + k0 + c * 8;
        cp_async16(dst,        Ah + so);
        cp_async16(dst + 8192, Al + so);
    }
    #pragma unroll
    for (int it = 0; it < 2; it++) {
        int i = tid + it * 256;
        int r = i >> 4, cn = i & 15;
        uint32_t dst = base + 16384 + r * 256 + (((cn ^ (r & 7))) << 4);
        size_t so = (size_t)(k0 + r) * N + cb + cn * 8;
        cp_async16(dst,        Bh + so);
        cp_async16(dst + 8192, Bl + so);
    }
}

__global__ __launch_bounds__(256)
void gemm_bf16tc(const __nv_bfloat16* __restrict__ Ah, const __nv_bfloat16* __restrict__ Al,
                 const __nv_bfloat16* __restrict__ Bh, const __nv_bfloat16* __restrict__ Bl,
                 float* __restrict__ C, int M, int N, int K) {
    extern __shared__ char smem[];
    uint32_t sb = (uint32_t)__cvta_generic_to_shared(smem);
    const int tid = threadIdx.x, lane = tid & 31, wid = tid >> 5;
    const int wm = wid >> 1, wn = wid & 1;
    const int gid = lane >> 2, tig = lane & 3;
    const int rb = blockIdx.y * GBM, cb = blockIdx.x * GBN;

    float acc[2][8][4];
    #pragma unroll
    for (int mt = 0; mt < 2; mt++)
        #pragma unroll
        for (int nt = 0; nt < 8; nt++)
            #pragma unroll
            for (int i = 0; i < 4; i++) acc[mt][nt][i] = 0.f;

    const int nk = K / GBK;
    gemm_issue_stage(sb, tid, Ah, Al, Bh, Bl, rb, cb, 0, K, N);
    asm volatile("cp.async.commit_group;\n" ::);
    if (nk > 1) {
        gemm_issue_stage(sb + STAGE_BYTES, tid, Ah, Al, Bh, Bl, rb, cb, GBK, K, N);
    }
    asm volatile("cp.async.commit_group;\n" ::);

    const int sub = lane >> 3, li = lane & 7;
    const int arow_off = ((sub & 1) ? 8 : 0) + li;
    const int akc_off  = (sub >> 1) ? 8 : 0;
    const int bk_off   = ((sub & 1) ? 8 : 0) + li;
    const int bn_off   = (sub >> 1) ? 8 : 0;

    for (int i = 0; i < nk; i++) {
        asm volatile("cp.async.wait_group 1;\n" ::);
        __syncthreads();
        const int st = i % GSTG;
        const uint32_t abase = sb + st * STAGE_BYTES;
        const uint32_t bbase = abase + 16384;
        if (i + 2 < nk)
            gemm_issue_stage(sb + ((i + 2) % GSTG) * STAGE_BYTES, tid,
                             Ah, Al, Bh, Bl, rb, cb, (i + 2) * GBK, K, N);
        asm volatile("cp.async.commit_group;\n" ::);

        #pragma unroll
        for (int kk = 0; kk < GBK; kk += 16) {
            unsigned bh[8][2], bl[8][2];
            #pragma unroll
            for (int np = 0; np < 4; np++) {
                int n0 = wn * 64 + np * 16;
                int k  = kk + bk_off;
                int n  = n0 + bn_off;
                uint32_t addr = bbase + k * 256 + ((((n >> 3) ^ (k & 7))) << 4);
                unsigned r_[4];
                LDSM4T(r_, addr);
                bh[np*2][0] = r_[0]; bh[np*2][1] = r_[1]; bh[np*2+1][0] = r_[2]; bh[np*2+1][1] = r_[3];
                LDSM4T(r_, addr + 8192);
                bl[np*2][0] = r_[0]; bl[np*2][1] = r_[1]; bl[np*2+1][0] = r_[2]; bl[np*2+1][1] = r_[3];
            }
            #pragma unroll
            for (int mt = 0; mt < 2; mt++) {
                int r0 = wm * 32 + mt * 16;
                int row  = r0 + arow_off;
                int kcol = kk + akc_off;
                uint32_t aaddr = abase + row * 64 + ((((kcol >> 3) ^ ((row >> 1) & 3))) << 4);
                unsigned ah[4], al[4];
                LDSM4(ah, aaddr);
                LDSM4(al, aaddr + 8192);
                #pragma unroll
                for (int nt = 0; nt < 8; nt++) {
                    mma16816(acc[mt][nt], ah, bh[nt]);
                    mma16816(acc[mt][nt], ah, bl[nt]);
                    mma16816(acc[mt][nt], al, bh[nt]);
                }
            }
        }
        __syncthreads();
    }

    #pragma unroll
    for (int mt = 0; mt < 2; mt++) {
        int r = rb + wm * 32 + mt * 16;
        #pragma unroll
        for (int nt = 0; nt < 8; nt++) {
            int c = cb + wn * 64 + nt * 8 + tig * 2;
            *(float2*)&C[(size_t)(r + gid    ) * N + c] = make_float2(acc[mt][nt][0], acc[mt][nt][1]);
            *(float2*)&C[(size_t)(r + gid + 8) * N + c] = make_float2(acc[mt][nt][2], acc[mt][nt][3]);
        }
    }
}

// ---------------- RoPE in place ----------------
__global__ void rope_kernel(float* __restrict__ x, const int* __restrict__ pos_ids,
                            const float* __restrict__ cosT, const float* __restrict__ sinT,
                            int nheads, int row_stride, int total) {
    int idx = blockIdx.x * blockDim.x + threadIdx.x;
    if (idx >= total) return;
    int d   = idx & 31;
    int h   = (idx >> 5) % nheads;
    int row = idx / (32 * nheads);
    int pos = pos_ids[row];
    float c1 = cosT[pos * 64 + d],      s1 = sinT[pos * 64 + d];
    float c2 = cosT[pos * 64 + d + 32], s2 = sinT[pos * 64 + d + 32];
    float* p = x + (size_t)row * row_stride + h * 64;
    float x1 = p[d], x2 = p[d + 32];
    p[d]      = x1 * c1 - x2 * s1;
    p[d + 32] = x2 * c2 + x1 * s2;
}

// ---------------- KB selection ----------------
__global__ void qsum_partial_kernel() {
    int b  = blockIdx.x, ch = blockIdx.y;
    int c  = threadIdx.x;
    int kh = c / CHD, dd = c % CHD;
    float s = 0.f;
    for (int q = ch * 64; q < ch * 64 + 64; q++) {
        const float* row = g_kbq + (size_t)(b * CQ + q) * (CNH * CHD);
        #pragma unroll
        for (int g = 0; g < CG; g++) s += row[(kh * CG + g) * CHD + dd];
    }
    g_qsum_part[(b * 16 + ch) * 512 + c] = s;
}

__global__ void qsum_combine_kernel() {
    int b = blockIdx.x, c = threadIdx.x;
    float s = 0.f;
    #pragma unroll
    for (int ch = 0; ch < 16; ch++) s += g_qsum_part[(b * 16 + ch) * 512 + c];
    g_qsum[b * 512 + c] = s;
}

__global__ void scores_kernel() {
    int gw = blockIdx.x * 8 + (threadIdx.x >> 5);
    int l  = threadIdx.x & 31;
    int b  = gw >> 9, n = gw & 511;
    const float* kr = g_kbkv + (size_t)(b * CKB + n) * 1024;
    const float* qs = g_qsum + b * 512;
    float s = 0.f;
    #pragma unroll
    for (int i = l; i < 512; i += 32) s = fmaf(kr[i], qs[i], s);
    #pragma unroll
    for (int o = 16; o > 0; o >>= 1) s += __shfl_xor_sync(0xffffffffu, s, o);
    if (l == 0) g_scores[b * CKB + n] = s;
}

__global__ void topk_kernel() {
    int b = blockIdx.x;
    __shared__ float sv[CKB];
    __shared__ float cv[16];
    __shared__ int   ci[16];
    int tid = threadIdx.x;
    sv[tid] = g_scores[b * CKB + tid];
    __syncthreads();
    for (int t = 0; t < CTOPK; t++) {
        float v = sv[tid]; int idx = tid;
        #pragma unroll
        for (int o = 16; o > 0; o >>= 1) {
            float ov = __shfl_xor_sync(0xffffffffu, v, o);
            int   oi = __shfl_xor_sync(0xffffffffu, idx, o);
            if (ov > v || (ov == v && oi < idx)) { v = ov; idx = oi; }
        }
        if ((tid & 31) == 0) { cv[tid >> 5] = v; ci[tid >> 5] = idx; }
        __syncthreads();
        if (tid < 32) {
            float v2 = (tid < 16) ? cv[tid] : -3.0e38f;
            int   i2 = (tid < 16) ? ci[tid] : 0x7fffffff;
            #pragma unroll
            for (int o = 16; o > 0; o >>= 1) {
                float ov = __shfl_xor_sync(0xffffffffu, v2, o);
                int   oi = __shfl_xor_sync(0xffffffffu, i2, o);
                if (ov > v2 || (ov == v2 && oi < i2)) { v2 = ov; i2 = oi; }
            }
            if (tid == 0) { g_topidx[b * CTOPK + t] = i2; sv[i2] = -3.0e38f; }
        }
        __syncthreads();
    }
}

// ---------------- tensor-core fused flash attention ----------------
// CTA: 64 queries x 1 head. 4 warps, warp = 16 q rows x 64 keys.
// smem: Qh 8K | Ql 8K | 2 stages x { Kh 8K | Kl 8K | Vh 8K | Vl 8K }
constexpr int ATT_SMEM = 16384 + 2 * 32768;

__device__ __forceinline__ void attn_load_tile(uint32_t st, int b, int kh, int ph2, int t, int tid) {
    for (int i = tid; i < 512; i += 128) {
        int r = i >> 3, c = i & 7;
        int kg = t * 64 + r;
        const __nv_bfloat16 *H, *L;
        size_t base;
        if (ph2 == 0) {
            int n = (kg < CTOPK) ? g_topidx[b * CTOPK + kg] : 0;
            base = (size_t)(b * CKB + n) * 1024 + kh * 64;
            H = s_kbkvh; L = s_kbkvl;
        } else {
            base = (size_t)(b * CQ + kg) * 1024 + kh * 64;
            H = s_kvh; L = s_kvl;
        }
        uint32_t d = st + r * 128 + ((c ^ (r & 7)) << 4);
        cp_async16(d,         H + base + c * 8);          // K hi
        cp_async16(d + 8192,  L + base + c * 8);          // K lo
        cp_async16(d + 16384, H + base + 512 + c * 8);    // V hi
        cp_async16(d + 24576, L + base + 512 + c * 8);    // V lo
    }
}

__global__ __launch_bounds__(128) void attn_tc_kernel() {
    extern __shared__ char asmem[];
    uint32_t sq = (uint32_t)__cvta_generic_to_shared(asmem);
    const int tid = threadIdx.x, lane = tid & 31, w = tid >> 5;
    const int gid = lane >> 2, tig = lane & 3;
    const int sub = lane >> 3, li = lane & 7;
    const int qt = blockIdx.x, h = blockIdx.y, b = blockIdx.z;
    const int kh = h >> 2;
    const int q0 = qt * 64;

    float m0 = -1e30f, m1 = -1e30f, l0 = 0.f, l1 = 0.f;
    float oacc[8][4];
    #pragma unroll
    for (int nt = 0; nt < 8; nt++)
        #pragma unroll
        for (int c = 0; c < 4; c++) oacc[nt][c] = 0.f;

    for (int ph2 = 0; ph2 < 2; ph2++) {
        __syncthreads();   // protect Q smem + stage buffers across phases
        const __nv_bfloat16* Qh = ph2 ? s_qh : s_kbqh;
        const __nv_bfloat16* Ql = ph2 ? s_ql : s_kbql;
        for (int i = tid; i < 512; i += 128) {
            int r = i >> 3, c = i & 7;
            uint32_t dst = sq + r * 128 + ((c ^ (r & 7)) << 4);
            size_t src = (size_t)(b * CQ + q0 + r) * 2048 + h * 64 + c * 8;
            cp_async16(dst,        Qh + src);
            cp_async16(dst + 8192, Ql + src);
        }
        const int ntiles = ph2 ? (qt + 1) : 2;
        attn_load_tile(sq + 16384, b, kh, ph2, 0, tid);
        asm volatile("cp.async.commit_group;\n" ::);

        for (int t = 0; t < ntiles; t++) {
            asm volatile("cp.async.wait_group 0;\n" ::);
            __syncthreads();
            if (t + 1 < ntiles) {
                attn_load_tile(sq + 16384 + ((t + 1) & 1) * 32768, b, kh, ph2, t + 1, tid);
                asm volatile("cp.async.commit_group;\n" ::);
            }
            const uint32_t stK = sq + 16384 + (t & 1) * 32768;
            const uint32_t stV = stK + 16384;

            // ---- S = Q @ K^T (3-pass hi/lo) ----
            float sacc[8][4];
            #pragma unroll
            for (int nt = 0; nt < 8; nt++)
                #pragma unroll
                for (int c = 0; c < 4; c++) sacc[nt][c] = 0.f;

            #pragma unroll
            for (int k16 = 0; k16 < 4; k16++) {
                int kk = k16 * 16;
                unsigned qa_h[4], qa_l[4];
                {
                    int row = w * 16 + (sub & 1) * 8 + li;
                    int ch  = (kk >> 3) + (sub >> 1);
                    uint32_t a = sq + row * 128 + ((ch ^ (row & 7)) << 4);
                    LDSM4(qa_h, a);
                    LDSM4(qa_l, a + 8192);
                }
                unsigned kb_h[8][2], kb_l[8][2];
                #pragma unroll
                for (int nt2 = 0; nt2 < 4; nt2++) {
                    int n  = nt2 * 16 + (sub >> 1) * 8 + li;
                    int ch = (kk >> 3) + (sub & 1);
                    uint32_t a = stK + n * 128 + ((ch ^ (n & 7)) << 4);
                    unsigned r_[4];
                    LDSM4(r_, a);
                    kb_h[nt2*2][0] = r_[0]; kb_h[nt2*2][1] = r_[1];
                    kb_h[nt2*2+1][0] = r_[2]; kb_h[nt2*2+1][1] = r_[3];
                    LDSM4(r_, a + 8192);
                    kb_l[nt2*2][0] = r_[0]; kb_l[nt2*2][1] = r_[1];
                    kb_l[nt2*2+1][0] = r_[2]; kb_l[nt2*2+1][1] = r_[3];
                }
                #pragma unroll
                for (int nt = 0; nt < 8; nt++) {
                    mma16816(sacc[nt], qa_h, kb_h[nt]);
                    mma16816(sacc[nt], qa_h, kb_l[nt]);
                    mma16816(sacc[nt], qa_l, kb_h[nt]);
                }
            }

            // ---- bias / mask (log2 domain) ----
            if (ph2 == 0) {
                #pragma unroll
                for (int nt = 0; nt < 8; nt++) {
                    int kg = t * 64 + nt * 8 + 2 * tig;
                    sacc[nt][0] = (kg     < CTOPK) ? sacc[nt][0] + KB_B2 : -1e30f;
                    sacc[nt][1] = (kg + 1 < CTOPK) ? sacc[nt][1] + KB_B2 : -1e30f;
                    sacc[nt][2] = (kg     < CTOPK) ? sacc[nt][2] + KB_B2 : -1e30f;
                    sacc[nt][3] = (kg + 1 < CTOPK) ? sacc[nt][3] + KB_B2 : -1e30f;
                }
            } else if (t == qt) {
                int rq0 = q0 + w * 16 + gid, rq1 = rq0 + 8;
                #pragma unroll
                for (int nt = 0; nt < 8; nt++) {
                    int kg = t * 64 + nt * 8 + 2 * tig;
                    if (kg     > rq0) sacc[nt][0] = -1e30f;
                    if (kg + 1 > rq0) sacc[nt][1] = -1e30f;
                    if (kg     > rq1) sacc[nt][2] = -1e30f;
                    if (kg + 1 > rq1) sacc[nt][3] = -1e30f;
                }
            }

            // ---- online softmax (base-2) ----
            float mx0 = -1e30f, mx1 = -1e30f;
            #pragma unroll
            for (int nt = 0; nt < 8; nt++) {
                mx0 = fmaxf(mx0, fmaxf(sacc[nt][0], sacc[nt][1]));
                mx1 = fmaxf(mx1, fmaxf(sacc[nt][2], sacc[nt][3]));
            }
            mx0 = fmaxf(mx0, __shfl_xor_sync(0xffffffffu, mx0, 1));
            mx0 = fmaxf(mx0, __shfl_xor_sync(0xffffffffu, mx0, 2));
            mx1 = fmaxf(mx1, __shfl_xor_sync(0xffffffffu, mx1, 1));
            mx1 = fmaxf(mx1, __shfl_xor_sync(0xffffffffu, mx1, 2));
            float mn0 = fmaxf(m0, mx0), mn1 = fmaxf(m1, mx1);
            float cr0 = fexp2(m0 - mn0), cr1 = fexp2(m1 - mn1);
            float sum0 = 0.f, sum1 = 0.f;
            #pragma unroll
            for (int nt = 0; nt < 8; nt++) {
                sacc[nt][0] = fexp2(sacc[nt][0] - mn0);
                sacc[nt][1] = fexp2(sacc[nt][1] - mn0);
                sacc[nt][2] = fexp2(sacc[nt][2] - mn1);
                sacc[nt][3] = fexp2(sacc[nt][3] - mn1);
                sum0 += sacc[nt][0] + sacc[nt][1];
                sum1 += sacc[nt][2] + sacc[nt][3];
                oacc[nt][0] *= cr0; oacc[nt][1] *= cr0;
                oacc[nt][2] *= cr1; oacc[nt][3] *= cr1;
            }
            sum0 += __shfl_xor_sync(0xffffffffu, sum0, 1);
            sum0 += __shfl_xor_sync(0xffffffffu, sum0, 2);
            sum1 += __shfl_xor_sync(0xffffffffu, sum1, 1);
            sum1 += __shfl_xor_sync(0xffffffffu, sum1, 2);
            l0 = l0 * cr0 + sum0;
            l1 = l1 * cr1 + sum1;
            m0 = mn0; m1 = mn1;

            // ---- O += P @ V (3-pass hi/lo, P from register acc) ----
            #pragma unroll
            for (int j = 0; j < 4; j++) {
                unsigned pa_h[4], pa_l[4];
                #pragma unroll
                for (int half = 0; half < 2; half++) {
                    float x0 = sacc[2*j+half][0], x1 = sacc[2*j+half][1];
                    float x2 = sacc[2*j+half][2], x3 = sacc[2*j+half][3];
                    __nv_bfloat162 hA = __floats2bfloat162_rn(x0, x1);
                    __nv_bfloat162 hB = __floats2bfloat162_rn(x2, x3);
                    float2 fA = __bfloat1622float2(hA), fB = __bfloat1622float2(hB);
                    __nv_bfloat162 lA = __floats2bfloat162_rn(x0 - fA.x, x1 - fA.y);
                    __nv_bfloat162 lB = __floats2bfloat162_rn(x2 - fB.x, x3 - fB.y);
                    pa_h[half*2]     = *(unsigned*)&hA;
                    pa_h[half*2 + 1] = *(unsigned*)&hB;
                    pa_l[half*2]     = *(unsigned*)&lA;
                    pa_l[half*2 + 1] = *(unsigned*)&lB;
                }
                unsigned vb_h[8][2], vb_l[8][2];
                #pragma unroll
                for (int nt2 = 0; nt2 < 4; nt2++) {
                    int k  = j * 16 + (sub & 1) * 8 + li;
                    int ch = nt2 * 2 + (sub >> 1);
                    uint32_t a = stV + k * 128 + ((ch ^ (k & 7)) << 4);
                    unsigned r_[4];
                    LDSM4T(r_, a);
                    vb_h[nt2*2][0] = r_[0]; vb_h[nt2*2][1] = r_[1];
                    vb_h[nt2*2+1][0] = r_[2]; vb_h[nt2*2+1][1] = r_[3];
                    LDSM4T(r_, a + 8192);
                    vb_l[nt2*2][0] = r_[0]; vb_l[nt2*2][1] = r_[1];
                    vb_l[nt2*2+1][0] = r_[2]; vb_l[nt2*2+1][1] = r_[3];
                }
                #pragma unroll
                for (int nt = 0; nt < 8; nt++) {
                    mma16816(oacc[nt], pa_h, vb_h[nt]);
                    mma16816(oacc[nt], pa_h, vb_l[nt]);
                    mma16816(oacc[nt], pa_l, vb_h[nt]);
                }
            }
        }
    }

    // ---- epilogue: normalize + write bf16 hi/lo directly ----
    float i0 = 1.f / l0, i1 = 1.f / l1;
    size_t row0 = (size_t)(b * CQ + q0 + w * 16 + gid) * 2048;
    size_t row1 = row0 + 8 * 2048;
    #pragma unroll
    for (int nt = 0; nt < 8; nt++) {
        int col = h * 64 + nt * 8 + 2 * tig;
        float y0 = oacc[nt][0] * i0, y1 = oacc[nt][1] * i0;
        float y2 = oacc[nt][2] * i1, y3 = oacc[nt][3] * i1;
        __nv_bfloat162 h0 = __floats2bfloat162_rn(y0, y1);
        float2 f0 = __bfloat1622float2(h0);
        __nv_bfloat162 lo0 = __floats2bfloat162_rn(y0 - f0.x, y1 - f0.y);
        __nv_bfloat162 h1v = __floats2bfloat162_rn(y2, y3);
        float2 f1 = __bfloat1622float2(h1v);
        __nv_bfloat162 lo1 = __floats2bfloat162_rn(y2 - f1.x, y3 - f1.y);
        *(__nv_bfloat162*)&s_at_h[row0 + col] = h0;
        *(__nv_bfloat162*)&s_at_l[row0 + col] = lo0;
        *(__nv_bfloat162*)&s_at_h[row1 + col] = h1v;
        *(__nv_bfloat162*)&s_at_l[row1 + col] = lo1;
    }
}

// ---------------- launch ----------------
static inline void launch_split(const float* in, __nv_bfloat16* oh, __nv_bfloat16* ol,
                                int rows, int cols, int ostride, int coff, float scale) {
    int total4 = rows * cols / 4;
    split_kernel<<<(total4 + 255) / 256, 256>>>(in, oh, ol, cols, ostride, coff, scale, total4);
}

extern "C" void kernel_launch(void* const* d_in, const int* in_sizes, int n_in,
                              void* d_out, int out_size) {
    const float* hs   = (const float*)d_in[0];
    const float* kb   = (const float*)d_in[1];
    const float* Wq   = (const float*)d_in[2];
    const float* Wk   = (const float*)d_in[3];
    const float* Wv   = (const float*)d_in[4];
    const float* Wo   = (const float*)d_in[5];
    const float* Wqn  = (const float*)d_in[6];
    const float* Wkbk = (const float*)d_in[7];
    const float* Wkbv = (const float*)d_in[8];
    const float* cosT = (const float*)d_in[9];
    const float* sinT = (const float*)d_in[10];
    const int*   pos  = (const int*)d_in[12];
    float* out = (float*)d_out;

    float *pq, *pkbq, *pkv, *pkbkv;
    cudaGetSymbolAddress((void**)&pq,    g_q);
    cudaGetSymbolAddress((void**)&pkbq,  g_kbq);
    cudaGetSymbolAddress((void**)&pkv,   g_kv);
    cudaGetSymbolAddress((void**)&pkbkv, g_kbkv);

    __nv_bfloat16 *hs_h, *hs_l, *kb_h, *kb_l, *at_h, *at_l;
    __nv_bfloat16 *wq_h, *wq_l, *wqn_h, *wqn_l, *wo_h, *wo_l, *wkv_h, *wkv_l, *wkb_h, *wkb_l;
    __nv_bfloat16 *qh, *ql, *kbqh, *kbql, *kvh, *kvl, *kbkvh, *kbkvl;
    cudaGetSymbolAddress((void**)&hs_h,  s_hs_h);  cudaGetSymbolAddress((void**)&hs_l,  s_hs_l);
    cudaGetSymbolAddress((void**)&kb_h,  s_kb_h);  cudaGetSymbolAddress((void**)&kb_l,  s_kb_l);
    cudaGetSymbolAddress((void**)&at_h,  s_at_h);  cudaGetSymbolAddress((void**)&at_l,  s_at_l);
    cudaGetSymbolAddress((void**)&wq_h,  s_wq_h);  cudaGetSymbolAddress((void**)&wq_l,  s_wq_l);
    cudaGetSymbolAddress((void**)&wqn_h, s_wqn_h); cudaGetSymbolAddress((void**)&wqn_l, s_wqn_l);
    cudaGetSymbolAddress((void**)&wo_h,  s_wo_h);  cudaGetSymbolAddress((void**)&wo_l,  s_wo_l);
    cudaGetSymbolAddress((void**)&wkv_h, s_wkv_h); cudaGetSymbolAddress((void**)&wkv_l, s_wkv_l);
    cudaGetSymbolAddress((void**)&wkb_h, s_wkb_h); cudaGetSymbolAddress((void**)&wkb_l, s_wkb_l);
    cudaGetSymbolAddress((void**)&qh,    s_qh);    cudaGetSymbolAddress((void**)&ql,    s_ql);
    cudaGetSymbolAddress((void**)&kbqh,  s_kbqh);  cudaGetSymbolAddress((void**)&kbql,  s_kbql);
    cudaGetSymbolAddress((void**)&kvh,   s_kvh);   cudaGetSymbolAddress((void**)&kvl,   s_kvl);
    cudaGetSymbolAddress((void**)&kbkvh, s_kbkvh); cudaGetSymbolAddress((void**)&kbkvl, s_kbkvl);

    static int attr_set = 0;
    if (!attr_set) {
        cudaFuncSetAttribute(gemm_bf16tc, cudaFuncAttributeMaxDynamicSharedMemorySize,
                             GSTG * STAGE_BYTES);
        cudaFuncSetAttribute(attn_tc_kernel, cudaFuncAttributeMaxDynamicSharedMemorySize,
                             ATT_SMEM);
        attr_set = 1;
    }

    const int M = CB * CQ;   // 2048

    // ---- input/weight splits ----
    launch_split(hs,   hs_h,  hs_l,  M,      CHID, CHID, 0,   1.f);
    launch_split(kb,   kb_h,  kb_l,  CB*CKB, CHID, CHID, 0,   1.f);
    launch_split(Wq,   wq_h,  wq_l,  CHID,   CHID, CHID, 0,   1.f);
    launch_split(Wqn,  wqn_h, wqn_l, CHID,   CHID, CHID, 0,   1.f);
    launch_split(Wo,   wo_h,  wo_l,  CHID,   CHID, CHID, 0,   1.f);
    launch_split(Wk,   wkv_h, wkv_l, CHID,   512,  1024, 0,   1.f);
    launch_split(Wv,   wkv_h, wkv_l, CHID,   512,  1024, 512, 1.f);
    launch_split(Wkbk, wkb_h, wkb_l, CHID,   512,  1024, 0,   1.f);
    launch_split(Wkbv, wkb_h, wkb_l, CHID,   512,  1024, 512, 1.f);

    const int SMEM = GSTG * STAGE_BYTES;
    // ---- projections ----
    gemm_bf16tc<<<dim3(CHID/GBN, M/GBM), 256, SMEM>>>(hs_h, hs_l, wq_h,  wq_l,  pq,    M, CHID, CHID);
    gemm_bf16tc<<<dim3(CHID/GBN, M/GBM), 256, SMEM>>>(hs_h, hs_l, wqn_h, wqn_l, pkbq,  M, CHID, CHID);
    gemm_bf16tc<<<dim3(1024/GBN, M/GBM), 256, SMEM>>>(hs_h, hs_l, wkv_h, wkv_l, pkv,   M, 1024, CHID);
    gemm_bf16tc<<<dim3(1024/GBN, (CB*CKB)/GBM), 256, SMEM>>>(kb_h, kb_l, wkb_h, wkb_l, pkbkv, CB*CKB, 1024, CHID);

    // ---- RoPE ----
    {
        int tq = CB * CQ * CNH * 32;
        rope_kernel<<<(tq + 255) / 256, 256>>>(pq, pos, cosT, sinT, CNH, CNH*CHD, tq);
        int tk = CB * CQ * CNKV * 32;
        rope_kernel<<<(tk + 255) / 256, 256>>>(pkv, pos, cosT, sinT, CNKV, 1024, tk);
    }

    // ---- attention operand splits (Q pre-scaled into log2 domain) ----
    launch_split(pq,    qh,    ql,    M,      CHID, CHID, 0, SCALE_L2E);
    launch_split(pkbq,  kbqh,  kbql,  M,      CHID, CHID, 0, SCALE_L2E);
    launch_split(pkv,   kvh,   kvl,   M,      1024, 1024, 0, 1.f);
    launch_split(pkbkv, kbkvh, kbkvl, CB*CKB, 1024, 1024, 0, 1.f);

    // ---- KB top-k ----
    qsum_partial_kernel<<<dim3(CB, 16), 512>>>();
    qsum_combine_kernel<<<CB, 512>>>();
    scores_kernel<<<(CB * CKB) / 8, 256>>>();
    topk_kernel<<<CB, 512>>>();

    // ---- tensor-core attention ----
    attn_tc_kernel<<<dim3(CQ / 64, CNH, CB), 128, ATT_SMEM>>>();

    // ---- output projection ----
    gemm_bf16tc<<<dim3(CHID/GBN, M/GBM), 256, SMEM>>>(at_h, at_l, wo_h, wo_l, out, M, CHID, CHID);
}